// round 1
// baseline (speedup 1.0000x reference)
#include <cuda_runtime.h>
#include <cstdint>
#include <cstddef>

// Problem constants
#define BATCH   2
#define NPTS    8192
#define DIM     128
#define KOUT    17            // K=16 + SAME_SOURCE skip handling: ranks 1..17
#define QT      128           // queries per CTA
#define CT      128           // candidates per tile
#define NTILES  (NPTS / CT)   // 64
#define LD      132           // smem row pitch (floats), 16B-aligned rows

// smem layout (floats)
#define OFF_QS   0
#define OFF_CS   (DIM * LD)                    // 16896
#define OFF_DS   (2 * DIM * LD)                // 33792
#define OFF_SQQ  (3 * DIM * LD)                // 50688
#define OFF_SQC  (3 * DIM * LD + QT)           // 50816
#define SMEM_FLOATS (3 * DIM * LD + QT + CT)   // 50944
#define SMEM_BYTES  (SMEM_FLOATS * 4)          // 203776

// Scratch (device globals: allocation-free rule)
__device__ float g_xT[BATCH * DIM * NPTS];   // x transposed: [b][k][n]
__device__ float g_sq[BATCH * NPTS];         // squared norms

// ---------------------------------------------------------------------------
// Prep kernel 1: tiled transpose x[b][n][k] -> g_xT[b][k][n]
// ---------------------------------------------------------------------------
__global__ void knn_transpose_kernel(const float* __restrict__ x) {
    __shared__ float t[32][33];
    const int b  = blockIdx.z;
    const int n0 = blockIdx.y * 32;
    const int k0 = blockIdx.x * 32;
    const int tx = threadIdx.x;   // 0..31
    const int ty = threadIdx.y;   // 0..7
#pragma unroll
    for (int i = 0; i < 32; i += 8)
        t[ty + i][tx] = x[((size_t)(b * NPTS + n0 + ty + i)) * DIM + k0 + tx];
    __syncthreads();
#pragma unroll
    for (int i = 0; i < 32; i += 8)
        g_xT[(size_t)b * DIM * NPTS + (size_t)(k0 + ty + i) * NPTS + n0 + tx] = t[tx][ty + i];
}

// ---------------------------------------------------------------------------
// Prep kernel 2: squared norms (one warp per point)
// ---------------------------------------------------------------------------
__global__ void knn_sq_kernel(const float* __restrict__ x) {
    const int n    = blockIdx.x * 8 + (threadIdx.x >> 5);
    const int lane = threadIdx.x & 31;
    float4 v = *(const float4*)(x + (size_t)n * DIM + lane * 4);
    float s = v.x * v.x + v.y * v.y + v.z * v.z + v.w * v.w;
#pragma unroll
    for (int o = 16; o > 0; o >>= 1) s += __shfl_xor_sync(0xFFFFFFFFu, s, o);
    if (lane == 0) g_sq[n] = s;
}

// ---------------------------------------------------------------------------
// Main fused GEMM + top-K kernel
// ---------------------------------------------------------------------------

// Try to insert (d2, idx) into register-resident sorted list bd[17]/bi[17].
// Comparator matches stable argsort: (d, idx) lexicographic. Constant indices
// only (fully unrolled) so lists stay in registers.
#define TRY_INSERT(dv, iv)                                                      \
    do {                                                                        \
        float _d = (dv);                                                        \
        if (_d <= th) {                                                         \
            int _i = (iv);                                                      \
            if (_d < bd[16] || (_d == bd[16] && _i < bi[16])) {                 \
                bd[16] = _d; bi[16] = _i;                                       \
                _Pragma("unroll")                                               \
                for (int _s = 16; _s > 0; --_s) {                               \
                    bool _sw = (bd[_s] < bd[_s - 1]) ||                         \
                               (bd[_s] == bd[_s - 1] && bi[_s] < bi[_s - 1]);   \
                    if (_sw) {                                                  \
                        float _td = bd[_s]; bd[_s] = bd[_s - 1]; bd[_s - 1] = _td; \
                        int _ti = bi[_s]; bi[_s] = bi[_s - 1]; bi[_s - 1] = _ti;  \
                    }                                                           \
                }                                                               \
                th = bd[16];                                                    \
            }                                                                   \
        }                                                                       \
    } while (0)

__global__ void __launch_bounds__(256, 1)
knn_main_kernel(float* __restrict__ outDist, float* __restrict__ outIdx) {
    extern __shared__ float sm[];
    float* Qs  = sm + OFF_QS;
    float* Cs  = sm + OFF_CS;
    float* Ds  = sm + OFF_DS;
    float* sqQ = sm + OFF_SQQ;
    float* sqC = sm + OFF_SQC;

    const int tid = threadIdx.x;
    const int b   = blockIdx.y;
    const int q0  = blockIdx.x * QT;
    const float* xT = g_xT + (size_t)b * DIM * NPTS;
    const float* sqg = g_sq + (size_t)b * NPTS;

    const float FINF = __int_as_float(0x7f800000);

    // ---- load Q tile (dim-major, conflict-free) ----
#pragma unroll
    for (int i = 0; i < 16; ++i) {
        int f = tid + i * 256;
        int k = f >> 5, c4 = f & 31;
        *(float4*)(Qs + k * LD + c4 * 4) = *(const float4*)(xT + (size_t)k * NPTS + q0 + c4 * 4);
    }
    if (tid < QT) sqQ[tid] = sqg[q0 + tid];

    // ---- top-K state (registers) ----
    float bd[KOUT]; int bi[KOUT];
#pragma unroll
    for (int s = 0; s < KOUT; ++s) { bd[s] = FINF; bi[s] = 0x7FFFFFFF; }
    float th = FINF;

    const int ty = tid >> 4, tx = tid & 15;          // GEMM 16x16 thread grid
    const int selR = tid >> 1, selC = (tid & 1) * 64; // selection: 2 threads/row

    for (int ct = 0; ct < NTILES; ++ct) {
        const int c0 = ct * CT;
        __syncthreads();
        // ---- load C tile ----
#pragma unroll
        for (int i = 0; i < 16; ++i) {
            int f = tid + i * 256;
            int k = f >> 5, c4 = f & 31;
            *(float4*)(Cs + k * LD + c4 * 4) = *(const float4*)(xT + (size_t)k * NPTS + c0 + c4 * 4);
        }
        if (tid < CT) sqC[tid] = sqg[c0 + tid];
        __syncthreads();

        // ---- 128x128x128 fp32 GEMM, 8x8 per thread ----
        float acc[8][8];
#pragma unroll
        for (int i = 0; i < 8; ++i)
#pragma unroll
            for (int j = 0; j < 8; ++j) acc[i][j] = 0.f;

#pragma unroll 8
        for (int kk = 0; kk < DIM; ++kk) {
            const float* qr = Qs + kk * LD + (ty << 3);
            const float* cr = Cs + kk * LD + (tx << 3);
            float4 a0 = *(const float4*)qr;
            float4 a1 = *(const float4*)(qr + 4);
            float4 b0 = *(const float4*)cr;
            float4 b1 = *(const float4*)(cr + 4);
            float ar[8] = {a0.x, a0.y, a0.z, a0.w, a1.x, a1.y, a1.z, a1.w};
            float br[8] = {b0.x, b0.y, b0.z, b0.w, b1.x, b1.y, b1.z, b1.w};
#pragma unroll
            for (int i = 0; i < 8; ++i)
#pragma unroll
                for (int j = 0; j < 8; ++j)
                    acc[i][j] = fmaf(ar[i], br[j], acc[i][j]);
        }

        // ---- epilogue: d2 = max(sqi + sqj - 2*dot, 0); self -> +inf ----
        float si[8], sj[8];
#pragma unroll
        for (int i = 0; i < 8; ++i) si[i] = sqQ[(ty << 3) + i];
#pragma unroll
        for (int j = 0; j < 8; ++j) sj[j] = sqC[(tx << 3) + j];
        const bool diagBlk = (c0 == q0);
#pragma unroll
        for (int i = 0; i < 8; ++i) {
            const int qg = q0 + (ty << 3) + i;
            float* drow = Ds + ((ty << 3) + i) * LD + (tx << 3);
#pragma unroll
            for (int g = 0; g < 8; g += 4) {
                float4 w;
                float d0 = fmaxf(fmaf(-2.f, acc[i][g + 0], si[i] + sj[g + 0]), 0.f);
                float d1 = fmaxf(fmaf(-2.f, acc[i][g + 1], si[i] + sj[g + 1]), 0.f);
                float d2 = fmaxf(fmaf(-2.f, acc[i][g + 2], si[i] + sj[g + 2]), 0.f);
                float d3 = fmaxf(fmaf(-2.f, acc[i][g + 3], si[i] + sj[g + 3]), 0.f);
                if (diagBlk) {
                    const int cg = c0 + (tx << 3) + g;
                    if (qg == cg + 0) d0 = FINF;
                    if (qg == cg + 1) d1 = FINF;
                    if (qg == cg + 2) d2 = FINF;
                    if (qg == cg + 3) d3 = FINF;
                }
                w.x = d0; w.y = d1; w.z = d2; w.w = d3;
                *(float4*)(drow + g) = w;
            }
        }
        __syncthreads();

        // ---- selection: each thread scans 64 d2 values of one query row ----
        const float* drow = Ds + selR * LD + selC;
#pragma unroll 1
        for (int j4 = 0; j4 < 16; ++j4) {
            float4 v = *(const float4*)(drow + j4 * 4);
            const int cb = c0 + selC + j4 * 4;
            TRY_INSERT(v.x, cb + 0);
            TRY_INSERT(v.y, cb + 1);
            TRY_INSERT(v.z, cb + 2);
            TRY_INSERT(v.w, cb + 3);
        }
    }

    // ---- merge half-lists, sqrt, stable resort by (d, idx), store ----
    __syncthreads();                       // selections done; alias Ds as scratch
    float* md = Ds;                        // 256*17 floats
    int*   mi = (int*)(Ds + 256 * KOUT);   // 256*17 ints (fits in Ds region)
#pragma unroll
    for (int s = 0; s < KOUT; ++s) { md[tid * KOUT + s] = bd[s]; mi[tid * KOUT + s] = bi[s]; }
    __syncthreads();

    if (tid < QT) {
        const float* da = md + (tid * 2) * KOUT;
        const int*   ia = mi + (tid * 2) * KOUT;
        const float* db = md + (tid * 2 + 1) * KOUT;
        const int*   ib = mi + (tid * 2 + 1) * KOUT;
        float od[KOUT]; int oi[KOUT];
        int pa = 0, pb = 0;
        for (int s = 0; s < KOUT; ++s) {   // pa+pb = s <= 16 before each iter: no OOB
            float d1 = da[pa]; int i1 = ia[pa];
            float d2 = db[pb]; int i2 = ib[pb];
            bool takeA = (d1 < d2) || (d1 == d2 && i1 < i2);
            if (takeA) { od[s] = d1; oi[s] = i1; ++pa; }
            else       { od[s] = d2; oi[s] = i2; ++pb; }
        }
        // sqrt (IEEE, matching jnp.sqrt), then resort by (sqrt(d2), idx) so the
        // output order matches the reference comparator even across sqrt ties.
        for (int s = 0; s < KOUT; ++s) od[s] = sqrtf(od[s]);
        for (int s = 1; s < KOUT; ++s) {
            float dv = od[s]; int iv = oi[s]; int t = s - 1;
            while (t >= 0 && (od[t] > dv || (od[t] == dv && oi[t] > iv))) {
                od[t + 1] = od[t]; oi[t + 1] = oi[t]; --t;
            }
            od[t + 1] = dv; oi[t + 1] = iv;
        }
        const size_t base = (size_t)(b * NPTS + q0 + tid) * KOUT;
        for (int s = 0; s < KOUT; ++s) {
            outDist[base + s] = od[s];
            if (outIdx) outIdx[base + s] = (float)oi[s];
        }
    }
}

// ---------------------------------------------------------------------------
// Launch
// ---------------------------------------------------------------------------
extern "C" void kernel_launch(void* const* d_in, const int* in_sizes, int n_in,
                              void* d_out, int out_size) {
    const float* x = (const float*)d_in[0];
    float* out = (float*)d_out;

    const int ND = BATCH * NPTS * KOUT;       // 278528
    const int XE = BATCH * NPTS * DIM;        // 2097152

    float* outDist = out;
    float* outIdx  = (out_size >= 2 * ND) ? (out + ND) : nullptr;

    cudaFuncSetAttribute(knn_main_kernel,
                         cudaFuncAttributeMaxDynamicSharedMemorySize, SMEM_BYTES);

    knn_transpose_kernel<<<dim3(DIM / 32, NPTS / 32, BATCH), dim3(32, 8)>>>(x);
    knn_sq_kernel<<<(BATCH * NPTS) / 8, 256>>>(x);
    knn_main_kernel<<<dim3(NPTS / QT, BATCH), 256, SMEM_BYTES>>>(outDist, outIdx);

    // Outputs 3 and 4 are x itself.
    if (out_size >= 2 * ND + 2 * XE) {
        cudaMemcpyAsync(out + 2 * ND, x, (size_t)XE * sizeof(float),
                        cudaMemcpyDeviceToDevice);
        cudaMemcpyAsync(out + 2 * ND + XE, x, (size_t)XE * sizeof(float),
                        cudaMemcpyDeviceToDevice);
    }
}